// round 14
// baseline (speedup 1.0000x reference)
#include <cuda_runtime.h>
#include <cuda_bf16.h>
#include <math.h>
#include <stdint.h>

// ---------------------------------------------------------------------------
//   B=2, T=1024, D=384 -> d=128, D3=384, D9=1152, NTOK=2048
//   GAMMA=5, EPS_W=1e-8, EPS_N=1e-5
// ---------------------------------------------------------------------------
#define NTOK 2048
#define D3   384
#define D9   1152
#define DD   128
#define HALF_GAMMA 2.5f
#define TANH_SAT 5.0f
#define NBINS 128
#define PAD  40
#define BAND_CAP 64

typedef unsigned long long u64;

// -------------------- device scratch (static, no allocs) -------------------
__device__ __align__(16) __nv_bfloat16 g_W1h[9  * 16384];
__device__ __align__(16) __nv_bfloat16 g_W1l[9  * 16384];
__device__ __align__(16) __nv_bfloat16 g_W2h[27 * 16384];
__device__ __align__(16) __nv_bfloat16 g_W2l[27 * 16384];
__device__ __align__(16) __nv_bfloat16 g_Ath[NTOK * D3];
__device__ __align__(16) __nv_bfloat16 g_Atl[NTOK * D3];
__device__ float g_fb  [3 * D3];
__device__ float g_QKV [NTOK * D9];
__device__ float g_h   [NTOK * D9];

// -------------------- helpers ----------------------------------------------
__device__ __forceinline__ float sp_fast(float w) {
    return fmaxf(w, 0.0f) + __logf(1.0f + __expf(-fabsf(w)));
}
__device__ __forceinline__ float fast_tanh(float x) {
    float y; asm("tanh.approx.f32 %0, %1;" : "=f"(y) : "f"(x)); return y;
}
__device__ __forceinline__ void wsplit(float v, uint16_t& h, uint16_t& l) {
    __nv_bfloat16 bh = __float2bfloat16(v);
    h = __bfloat16_as_ushort(bh);
    l = __bfloat16_as_ushort(__float2bfloat16(v - __bfloat162float(bh)));
}
__device__ __forceinline__ uint32_t ld32(const __nv_bfloat16* p, int eoff) {
    return *(const uint32_t*)(p + eoff);
}
__device__ __forceinline__ void mma16816(float* c, const uint32_t* a,
                                         uint32_t b0, uint32_t b1) {
    asm volatile(
        "mma.sync.aligned.m16n8k16.row.col.f32.bf16.bf16.f32 "
        "{%0,%1,%2,%3}, {%4,%5,%6,%7}, {%8,%9}, {%0,%1,%2,%3};"
        : "+f"(c[0]), "+f"(c[1]), "+f"(c[2]), "+f"(c[3])
        : "r"(a[0]), "r"(a[1]), "r"(a[2]), "r"(a[3]), "r"(b0), "r"(b1));
}

// -------------------- K0: merged prep (fuse / fbias / Wp tiles) -------------
__global__ __launch_bounds__(384) void k_prep(
        const float* __restrict__ Wq, const float* __restrict__ Wk,
        const float* __restrict__ Wv,
        const float* __restrict__ Sq, const float* __restrict__ Sk,
        const float* __restrict__ Sv,
        const float* __restrict__ bq, const float* __restrict__ bk,
        const float* __restrict__ bv,
        const float* __restrict__ Wp) {
    __shared__ float4 ssw[D3];
    const int tid = threadIdx.x;
    const int blk = blockIdx.x;

    if (blk < 96) {
        const int g  = blk >> 5;
        const int k0 = (blk & 31) * 4;
        const float* W = (g == 0) ? Wq : (g == 1) ? Wk : Wv;
        const float* S = (g == 0) ? Sq : (g == 1) ? Sk : Sv;

        float4 w = *(const float4*)(W + tid * DD + k0);
        w.x = sp_fast(w.x); w.y = sp_fast(w.y);
        w.z = sp_fast(w.z); w.w = sp_fast(w.w);
        ssw[tid] = w;
        __syncthreads();

        float acc[4] = {0.f, 0.f, 0.f, 0.f};
#pragma unroll 8
        for (int m = 0; m < D3; m++) {
            float s  = S[m * D3 + tid];
            float4 c = ssw[m];
            acc[0] = fmaf(s, c.x, acc[0]);
            acc[1] = fmaf(s, c.y, acc[1]);
            acc[2] = fmaf(s, c.z, acc[2]);
            acc[3] = fmaf(s, c.w, acc[3]);
        }
        const int ntile = g * 3 + (tid >> 7);
        const int nr    = tid & 127;
        uint16_t h[4], l[4];
#pragma unroll
        for (int j = 0; j < 4; j++) wsplit(acc[j], h[j], l[j]);
        u64 H = (u64)h[0] | ((u64)h[1] << 16) | ((u64)h[2] << 32) | ((u64)h[3] << 48);
        u64 L = (u64)l[0] | ((u64)l[1] << 16) | ((u64)l[2] << 32) | ((u64)l[3] << 48);
        size_t off = (size_t)ntile * 16384 + nr * 128 + k0;
        *(u64*)(g_W1h + off) = H;
        *(u64*)(g_W1l + off) = L;
    } else if (blk < 192) {
        const int w    = (blk - 96) * 12 + (tid >> 5);
        const int lane = tid & 31;
        const int g = w / D3, o = w - g * D3;
        const float* S = (g == 0) ? Sq : (g == 1) ? Sk : Sv;
        const float* b = (g == 0) ? bq : (g == 1) ? bk : bv;
        float acc = 0.0f;
#pragma unroll
        for (int i = 0; i < 12; i++) {
            int m = lane + i * 32;
            acc = fmaf(S[m * D3 + o], b[m], acc);
        }
#pragma unroll
        for (int off = 16; off > 0; off >>= 1)
            acc += __shfl_down_sync(0xffffffffu, acc, off);
        if (lane == 0) g_fb[w] = acc;
    } else {
        const int b = blk - 192;
        const int k = tid;
#pragma unroll
        for (int r = 0; r < 12; r++) {
            int o = b * 12 + r;
            float v = sp_fast(Wp[o * D3 + k]);
            uint16_t h, l;
            wsplit(v, h, l);
            size_t off = (size_t)((k >> 7) * 9 + (o >> 7)) * 16384
                       + (o & 127) * 128 + (k & 127);
            g_W2h[off] = __ushort_as_bfloat16(h);
            g_W2l[off] = __ushort_as_bfloat16(l);
        }
    }
}

// -------------------- K1/K3: HMMA dual-bf16 GEMM, M-tile 64, 2 CTA/SM -------
// C[2048,1152] = A[2048,384] @ W[384,1152] + bias  (AhBh + AhBl + AlBh)
// grid (32, 9); 8 warps = 2(m) x 4(n); warp tile 32x32.
template <int MODE>
__global__ __launch_bounds__(256, 2) void k_gemm_mma(const float* __restrict__ Ax,
                                                     const float* __restrict__ bext) {
    __shared__ __nv_bfloat16 sAh[64 * PAD];
    __shared__ __nv_bfloat16 sAl[64 * PAD];
    __shared__ __nv_bfloat16 sBh[128 * PAD];
    __shared__ __nv_bfloat16 sBl[128 * PAD];

    const int tid  = threadIdx.x;
    const int lane = tid & 31, wid = tid >> 5;
    const int g    = lane >> 2, tig = lane & 3;
    const int wm   = wid & 1,  wn  = wid >> 1;       // 2(m) x 4(n)
    const int m0   = wm * 32,  n0  = wn * 32;
    const int t0   = blockIdx.x * 64;
    const int jn   = blockIdx.y;

    const __nv_bfloat16* Wh = (MODE == 0) ? g_W1h : g_W2h;
    const __nv_bfloat16* Wl = (MODE == 0) ? g_W1l : g_W2l;
    float*       Cout = (MODE == 0) ? g_QKV : g_h;
    const float* bias = (MODE == 0) ? g_fb  : bext;
    const int nch = (MODE == 0) ? 4 : 12;

    float acc[2][4][4];
#pragma unroll
    for (int f = 0; f < 2; f++)
#pragma unroll
        for (int nf = 0; nf < 4; nf++)
#pragma unroll
            for (int i = 0; i < 4; i++) acc[f][nf][i] = 0.f;

    float4 afr[2];       // MODE 0: fp32 A prefetch (64x32 = 512 float4)
    uint4  pfr[6];       // 0-3: B hi/lo (512 uint4); 4-5: A hi/lo (MODE 1)

    auto ldch = [&](int ch) {
        const int acol  = (MODE == 0) ? ((jn / 3) * 128 + ch * 32) : (ch * 32);
        const int wtile = (MODE == 0) ? jn : ((ch >> 2) * 9 + jn);
        const int wcol  = (MODE == 0) ? (ch * 32) : ((ch & 3) * 32);
        if (MODE == 0) {
#pragma unroll
            for (int j = 0; j < 2; j++) {
                int idx = tid + (j << 8);                // 512 float4
                int row = idx >> 3, k4 = (idx & 7) << 2;
                afr[j] = *(const float4*)(Ax + (size_t)(t0 + row) * D3 + acol + k4);
            }
        } else {
            int row = tid >> 2, seg = (tid & 3) << 3;    // 256 uint4 each
            pfr[4] = *(const uint4*)(g_Ath + (size_t)(t0 + row) * D3 + acol + seg);
            pfr[5] = *(const uint4*)(g_Atl + (size_t)(t0 + row) * D3 + acol + seg);
        }
#pragma unroll
        for (int j = 0; j < 4; j++) {                    // B: 512 uint4 each
            int idx = tid + ((j & 1) << 8);
            int row = idx >> 2, seg = (idx & 3) << 3;
            const __nv_bfloat16* src = ((j < 2) ? Wh : Wl)
                + (size_t)wtile * 16384 + row * 128 + wcol + seg;
            pfr[j] = *(const uint4*)src;
        }
    };
    auto stch = [&]() {
        if (MODE == 0) {
#pragma unroll
            for (int j = 0; j < 2; j++) {
                int idx = tid + (j << 8);
                int row = idx >> 3, k4 = (idx & 7) << 2;
                uint16_t h0, l0, h1, l1, h2, l2, h3, l3;
                wsplit(afr[j].x, h0, l0); wsplit(afr[j].y, h1, l1);
                wsplit(afr[j].z, h2, l2); wsplit(afr[j].w, h3, l3);
                u64 H = (u64)h0 | ((u64)h1 << 16) | ((u64)h2 << 32) | ((u64)h3 << 48);
                u64 L = (u64)l0 | ((u64)l1 << 16) | ((u64)l2 << 32) | ((u64)l3 << 48);
                *(u64*)(sAh + row * PAD + k4) = H;
                *(u64*)(sAl + row * PAD + k4) = L;
            }
        } else {
            int row = tid >> 2, seg = (tid & 3) << 3;
            *(uint4*)(sAh + row * PAD + seg) = pfr[4];
            *(uint4*)(sAl + row * PAD + seg) = pfr[5];
        }
#pragma unroll
        for (int j = 0; j < 4; j++) {
            int idx = tid + ((j & 1) << 8);
            int row = idx >> 2, seg = (idx & 3) << 3;
            *(uint4*)(((j < 2) ? sBh : sBl) + row * PAD + seg) = pfr[j];
        }
    };

    ldch(0);
    for (int ch = 0; ch < nch; ch++) {
        stch();
        __syncthreads();
        if (ch + 1 < nch) ldch(ch + 1);

#pragma unroll
        for (int kk = 0; kk < 32; kk += 16) {
            uint32_t ah[2][4], al[2][4];
#pragma unroll
            for (int f = 0; f < 2; f++) {
                int r0 = m0 + f * 16 + g;
                int co = kk + tig * 2;
                ah[f][0] = ld32(sAh, r0 * PAD + co);
                ah[f][1] = ld32(sAh, (r0 + 8) * PAD + co);
                ah[f][2] = ld32(sAh, r0 * PAD + co + 8);
                ah[f][3] = ld32(sAh, (r0 + 8) * PAD + co + 8);
                al[f][0] = ld32(sAl, r0 * PAD + co);
                al[f][1] = ld32(sAl, (r0 + 8) * PAD + co);
                al[f][2] = ld32(sAl, r0 * PAD + co + 8);
                al[f][3] = ld32(sAl, (r0 + 8) * PAD + co + 8);
            }
#pragma unroll
            for (int nf = 0; nf < 4; nf++) {
                int nb = (n0 + nf * 8 + g) * PAD + kk + tig * 2;
                uint32_t bh0 = ld32(sBh, nb);
                uint32_t bh1 = ld32(sBh, nb + 8);
                uint32_t bl0 = ld32(sBl, nb);
                uint32_t bl1 = ld32(sBl, nb + 8);
#pragma unroll
                for (int f = 0; f < 2; f++) {
                    mma16816(acc[f][nf], ah[f], bh0, bh1);
                    mma16816(acc[f][nf], ah[f], bl0, bl1);
                    mma16816(acc[f][nf], al[f], bh0, bh1);
                }
            }
        }
        __syncthreads();
    }

#pragma unroll
    for (int f = 0; f < 2; f++) {
        int row = t0 + m0 + f * 16 + g;
#pragma unroll
        for (int nf = 0; nf < 4; nf++) {
            int col = jn * 128 + n0 + nf * 8 + tig * 2;
            float b0v = bias[col], b1v = bias[col + 1];
            float2 lo = make_float2(acc[f][nf][0] + b0v, acc[f][nf][1] + b1v);
            float2 hi = make_float2(acc[f][nf][2] + b0v, acc[f][nf][3] + b1v);
            *(float2*)(Cout + (size_t)row * D9 + col)       = lo;
            *(float2*)(Cout + (size_t)(row + 8) * D9 + col) = hi;
        }
    }
}

// -------------------- K2: prefix-band attention (bin tails + tier-2) --------
__global__ __launch_bounds__(384) void k_attn() {
    __shared__ float2 s[D3];
    __shared__ int    off[NBINS + 1];
    __shared__ int    cnt[NBINS],  cur[NBINS];
    __shared__ int    qcnt[NBINS], qcur[NBINS];
    __shared__ float  binS[NBINS], binSV[NBINS];
    __shared__ float  PS[NBINS + 1], PSV[NBINS + 1];
    __shared__ int    wtot[4], qwtot[4];
    __shared__ float2 fwtot[4];
    __shared__ float  rmax[12], rsum[12];
    __shared__ float  s_inv, s_sumv;
    __shared__ float  sqv[D3];
    __shared__ int    qlist[D3];
    __shared__ int    biglist[D3];
    __shared__ int    bigcount;
    __shared__ float  satt[D3];

    const int t    = blockIdx.x;
    const int tid  = threadIdx.x;
    const int lane = tid & 31, wid = tid >> 5;
    const float* base = g_QKV + (size_t)t * D9;

    const float q  = base[tid];
    const float c  = base[D3 + tid] * HALF_GAMMA;
    const float v  = base[2 * D3 + tid];
    const float ac = fabsf(c);
    const float sg = (c >= 0.f) ? 1.f : -1.f;
    sqv[tid] = q;

    float mx = ac, sv = v;
#pragma unroll
    for (int o = 16; o > 0; o >>= 1) {
        mx = fmaxf(mx, __shfl_down_sync(0xffffffffu, mx, o));
        sv += __shfl_down_sync(0xffffffffu, sv, o);
    }
    if (lane == 0) { rmax[wid] = mx; rsum[wid] = sv; }
    if (tid < NBINS) {
        cnt[tid] = 0; qcnt[tid] = 0;
        binS[tid] = 0.f; binSV[tid] = 0.f;
    }
    if (tid == 0) bigcount = 0;
    __syncthreads();
    if (tid == 0) {
        float m = rmax[0], s2 = rsum[0];
#pragma unroll
        for (int i = 1; i < 12; i++) { m = fmaxf(m, rmax[i]); s2 += rsum[i]; }
        s_inv  = 127.99f / (m + 1e-12f);
        s_sumv = s2;
    }
    __syncthreads();
    const float inv = s_inv;

    const int b  = (int)(ac * inv);
    const float th = TANH_SAT / fabsf(q);
    const int bt = (int)fminf(th * inv, 127.0f);
    atomicAdd(&cnt[b], 1);
    atomicAdd(&qcnt[bt], 1);
    atomicAdd(&binS[b], sg);
    atomicAdd(&binSV[b], sg * v);
    __syncthreads();

    // triple scan: warps 0-3 cnt, 4-7 qcnt, 8-11 float2(binS,binSV)
    if (wid < 8) {
        int i2 = tid & 127;
        int xval = (wid < 4) ? cnt[i2] : qcnt[i2];
        int incl = xval;
#pragma unroll
        for (int o = 1; o < 32; o <<= 1) {
            int nb = __shfl_up_sync(0xffffffffu, incl, o);
            if (lane >= o) incl += nb;
        }
        if (lane == 31) {
            if (wid < 4) wtot[wid] = incl;
            else         qwtot[wid - 4] = incl;
        }
        __syncthreads();
        int wq = wid & 3;
        int add = 0;
        const int* tot = (wid < 4) ? wtot : qwtot;
#pragma unroll
        for (int w = 0; w < 4; w++) if (w < wq) add += tot[w];
        if (wid < 4) {
            off[i2 + 1] = incl + add;
            cur[i2]     = incl + add - xval;
            if (i2 == 0) off[0] = 0;
        } else {
            qcur[i2] = incl + add - xval;
        }
    } else {
        int i2 = tid - 256;
        float iS = binS[i2], iV = binSV[i2];
#pragma unroll
        for (int o = 1; o < 32; o <<= 1) {
            float ax = __shfl_up_sync(0xffffffffu, iS, o);
            float ay = __shfl_up_sync(0xffffffffu, iV, o);
            if (lane >= o) { iS += ax; iV += ay; }
        }
        if (lane == 31) fwtot[wid - 8] = make_float2(iS, iV);
        __syncthreads();
        int wq = wid - 8;
        float aS = 0.f, aV = 0.f;
#pragma unroll
        for (int w = 0; w < 4; w++)
            if (w < wq) { aS += fwtot[w].x; aV += fwtot[w].y; }
        PS [i2 + 1] = iS + aS;
        PSV[i2 + 1] = iV + aV;
        if (i2 == 0) { PS[0] = 0.f; PSV[0] = 0.f; }
    }
    __syncthreads();

    {
        int pos = atomicAdd(&cur[b], 1);
        s[pos] = make_float2(c, v);
        int n  = off[bt + 1];
        int qpos = atomicAdd(&qcur[bt], 1);
        qlist[qpos] = tid | (n << 9) | (bt << 18);
    }
    __syncthreads();

    // tier 1: lanes ordered by bt -> similar n; big bands (n > CAP) deferred
    const int   e   = qlist[tid];
    const int   qi  = e & 511;
    const int   nn  = (e >> 9) & 511;
    const int   btq = (e >> 18) & 127;
    const float qq  = sqv[qi];
    const int   nn1 = (nn <= BAND_CAP) ? nn : 0;
    int nmax = nn1;
#pragma unroll
    for (int o = 16; o > 0; o >>= 1)
        nmax = max(nmax, __shfl_xor_sync(0xffffffffu, nmax, o));

    float ts = 0.f, tv = 0.f;
#pragma unroll 4
    for (int j = 0; j < nmax; j++) {
        float2 cv = s[j];
        if (j < nn1) {
            float tt = fast_tanh(qq * cv.x);
            tv = fmaf(tt, cv.y, tv);
            ts += tt;
        }
    }
    if (nn <= BAND_CAP) {
        const float sgq = (qq >= 0.f) ? 1.f : -1.f;
        ts += sgq * (PS [NBINS] - PS [btq + 1]);
        tv += sgq * (PSV[NBINS] - PSV[btq + 1]);
        float num = fmaf(0.5f, tv, 0.5f * s_sumv);
        float den = fmaf(0.5f, ts, 192.0f + 1e-8f);
        satt[qi] = num / den;
    } else {
        int idx = atomicAdd(&bigcount, 1);
        biglist[idx] = e;
    }
    __syncthreads();

    // tier 2: one warp per large-band query, lanes stride the prefix
    const int nbig = bigcount;
    for (int b2 = wid; b2 < nbig; b2 += 12) {
        const int e2  = biglist[b2];
        const int qi2 = e2 & 511;
        const int nn2 = (e2 >> 9) & 511;
        const int bt2 = (e2 >> 18) & 127;
        const float qq2 = sqv[qi2];
        float ts2 = 0.f, tv2 = 0.f;
        for (int j = lane; j < nn2; j += 32) {
            float2 cv = s[j];
            float tt = fast_tanh(qq2 * cv.x);
            tv2 = fmaf(tt, cv.y, tv2);
            ts2 += tt;
        }
#pragma unroll
        for (int o = 16; o > 0; o >>= 1) {
            tv2 += __shfl_down_sync(0xffffffffu, tv2, o);
            ts2 += __shfl_down_sync(0xffffffffu, ts2, o);
        }
        if (lane == 0) {
            const float sgq = (qq2 >= 0.f) ? 1.f : -1.f;
            ts2 += sgq * (PS [NBINS] - PS [bt2 + 1]);
            tv2 += sgq * (PSV[NBINS] - PSV[bt2 + 1]);
            float num = fmaf(0.5f, tv2, 0.5f * s_sumv);
            float den = fmaf(0.5f, ts2, 192.0f + 1e-8f);
            satt[qi2] = num / den;
        }
    }
    __syncthreads();

    uint16_t hh, ll;
    wsplit(satt[tid], hh, ll);
    g_Ath[(size_t)t * D3 + tid] = __ushort_as_bfloat16(hh);
    g_Atl[(size_t)t * D3 + tid] = __ushort_as_bfloat16(ll);
}

// -------------------- K4: LayerNorm, 2 tokens/CTA, two-pass -----------------
__global__ __launch_bounds__(384) void k_ln(const float* __restrict__ gn,
                                            const float* __restrict__ bn,
                                            float* __restrict__ out) {
    __shared__ float red[2][6];
    __shared__ float stat[2][2];
    const int tid  = threadIdx.x;
    const int wid  = tid >> 5, lane = tid & 31;
    const int half = (wid >= 6);
    const int widh = wid - half * 6;
    const int tidh = tid - half * 192;
    const int t    = blockIdx.x * 2 + half;
    const float* h = g_h + (size_t)t * D9;

    float v[6];
#pragma unroll
    for (int j = 0; j < 6; j++) v[j] = h[tidh + 192 * j];

    float s = 0.f;
#pragma unroll
    for (int j = 0; j < 6; j++) s += v[j];
#pragma unroll
    for (int o = 16; o > 0; o >>= 1) s += __shfl_down_sync(0xffffffffu, s, o);
    if (lane == 0) red[half][widh] = s;
    __syncthreads();
    if (tidh == 0) {
        float tot = 0.f;
#pragma unroll
        for (int i = 0; i < 6; i++) tot += red[half][i];
        stat[half][0] = tot * (1.0f / 1152.0f);
    }
    __syncthreads();
    const float mu = stat[half][0];

    float d[6];
    float ss = 0.f;
#pragma unroll
    for (int j = 0; j < 6; j++) { d[j] = v[j] - mu; ss += d[j] * d[j]; }
#pragma unroll
    for (int o = 16; o > 0; o >>= 1) ss += __shfl_down_sync(0xffffffffu, ss, o);
    if (lane == 0) red[half][widh] = ss;
    __syncthreads();
    if (tidh == 0) {
        float tot = 0.f;
#pragma unroll
        for (int i = 0; i < 6; i++) tot += red[half][i];
        stat[half][1] = rsqrtf(tot * (1.0f / 1152.0f) + 1e-5f);
    }
    __syncthreads();
    const float rs = stat[half][1];

    float* o = out + (size_t)t * D9;
#pragma unroll
    for (int j = 0; j < 6; j++) {
        int idx = tidh + 192 * j;
        o[idx] = d[j] * rs * gn[idx] + bn[idx];
    }
}

// -------------------- launch -------------------------------------------------
extern "C" void kernel_launch(void* const* d_in, const int* in_sizes, int n_in,
                              void* d_out, int out_size) {
    const float* x  = (const float*)d_in[0];
    const float* Wq = (const float*)d_in[1];
    const float* bq = (const float*)d_in[2];
    const float* Sq = (const float*)d_in[3];
    const float* Wk = (const float*)d_in[4];
    const float* bk = (const float*)d_in[5];
    const float* Sk = (const float*)d_in[6];
    const float* Wv = (const float*)d_in[7];
    const float* bv = (const float*)d_in[8];
    const float* Sv = (const float*)d_in[9];
    const float* Wp = (const float*)d_in[10];
    const float* bp = (const float*)d_in[11];
    const float* gn = (const float*)d_in[12];
    const float* bn = (const float*)d_in[13];
    float* out = (float*)d_out;

    // 5 launches; profiled slot (#4) = retiled k_gemm_mma<1>
    k_prep       <<<288, 384>>>(Wq, Wk, Wv, Sq, Sk, Sv, bq, bk, bv, Wp);
    k_gemm_mma<0><<<dim3(32, 9), 256>>>(x, nullptr);
    k_attn       <<<NTOK, 384>>>();
    k_gemm_mma<1><<<dim3(32, 9), 256>>>(nullptr, bp);
    k_ln         <<<NTOK / 2, 384>>>(gn, bn, out);
}

// round 15
// speedup vs baseline: 1.3910x; 1.3910x over previous
#include <cuda_runtime.h>
#include <cuda_bf16.h>
#include <math.h>
#include <stdint.h>

// ---------------------------------------------------------------------------
//   B=2, T=1024, D=384 -> d=128, D3=384, D9=1152, NTOK=2048
//   GAMMA=5, EPS_W=1e-8, EPS_N=1e-5
// ---------------------------------------------------------------------------
#define NTOK 2048
#define D3   384
#define D9   1152
#define DD   128
#define HALF_GAMMA 2.5f
#define TANH_SAT 5.0f
#define NBINS 128
#define PAD  40              // bf16 elems per smem row (80B): LDSM conflict-free

typedef unsigned long long u64;

// -------------------- device scratch (static, no allocs) -------------------
__device__ __align__(16) __nv_bfloat16 g_W1h[9  * 16384];
__device__ __align__(16) __nv_bfloat16 g_W1l[9  * 16384];
__device__ __align__(16) __nv_bfloat16 g_W2h[27 * 16384];
__device__ __align__(16) __nv_bfloat16 g_W2l[27 * 16384];
__device__ __align__(16) __nv_bfloat16 g_Ath[NTOK * D3];
__device__ __align__(16) __nv_bfloat16 g_Atl[NTOK * D3];
__device__ float g_fb  [3 * D3];
__device__ float g_QKV [NTOK * D9];
__device__ float g_h   [NTOK * D9];

// -------------------- helpers ----------------------------------------------
__device__ __forceinline__ float sp_fast(float w) {
    return fmaxf(w, 0.0f) + __logf(1.0f + __expf(-fabsf(w)));
}
__device__ __forceinline__ float fast_tanh(float x) {
    float y; asm("tanh.approx.f32 %0, %1;" : "=f"(y) : "f"(x)); return y;
}
__device__ __forceinline__ void wsplit(float v, uint16_t& h, uint16_t& l) {
    __nv_bfloat16 bh = __float2bfloat16(v);
    h = __bfloat16_as_ushort(bh);
    l = __bfloat16_as_ushort(__float2bfloat16(v - __bfloat162float(bh)));
}
__device__ __forceinline__ void mma16816(float* c, const uint32_t* a,
                                         uint32_t b0, uint32_t b1) {
    asm volatile(
        "mma.sync.aligned.m16n8k16.row.col.f32.bf16.bf16.f32 "
        "{%0,%1,%2,%3}, {%4,%5,%6,%7}, {%8,%9}, {%0,%1,%2,%3};"
        : "+f"(c[0]), "+f"(c[1]), "+f"(c[2]), "+f"(c[3])
        : "r"(a[0]), "r"(a[1]), "r"(a[2]), "r"(a[3]), "r"(b0), "r"(b1));
}
__device__ __forceinline__ void ldsm4(uint32_t* r, uint32_t saddr) {
    asm volatile("ldmatrix.sync.aligned.m8n8.x4.shared.b16 {%0,%1,%2,%3}, [%4];"
        : "=r"(r[0]), "=r"(r[1]), "=r"(r[2]), "=r"(r[3]) : "r"(saddr));
}

// -------------------- K0: merged prep (fuse / fbias / Wp tiles) -------------
__global__ __launch_bounds__(384) void k_prep(
        const float* __restrict__ Wq, const float* __restrict__ Wk,
        const float* __restrict__ Wv,
        const float* __restrict__ Sq, const float* __restrict__ Sk,
        const float* __restrict__ Sv,
        const float* __restrict__ bq, const float* __restrict__ bk,
        const float* __restrict__ bv,
        const float* __restrict__ Wp) {
    __shared__ float4 ssw[D3];
    const int tid = threadIdx.x;
    const int blk = blockIdx.x;

    if (blk < 96) {
        const int g  = blk >> 5;
        const int k0 = (blk & 31) * 4;
        const float* W = (g == 0) ? Wq : (g == 1) ? Wk : Wv;
        const float* S = (g == 0) ? Sq : (g == 1) ? Sk : Sv;

        float4 w = *(const float4*)(W + tid * DD + k0);
        w.x = sp_fast(w.x); w.y = sp_fast(w.y);
        w.z = sp_fast(w.z); w.w = sp_fast(w.w);
        ssw[tid] = w;
        __syncthreads();

        float acc[4] = {0.f, 0.f, 0.f, 0.f};
#pragma unroll 8
        for (int m = 0; m < D3; m++) {
            float s  = S[m * D3 + tid];
            float4 c = ssw[m];
            acc[0] = fmaf(s, c.x, acc[0]);
            acc[1] = fmaf(s, c.y, acc[1]);
            acc[2] = fmaf(s, c.z, acc[2]);
            acc[3] = fmaf(s, c.w, acc[3]);
        }
        const int ntile = g * 3 + (tid >> 7);
        const int nr    = tid & 127;
        uint16_t h[4], l[4];
#pragma unroll
        for (int j = 0; j < 4; j++) wsplit(acc[j], h[j], l[j]);
        u64 H = (u64)h[0] | ((u64)h[1] << 16) | ((u64)h[2] << 32) | ((u64)h[3] << 48);
        u64 L = (u64)l[0] | ((u64)l[1] << 16) | ((u64)l[2] << 32) | ((u64)l[3] << 48);
        size_t off = (size_t)ntile * 16384 + nr * 128 + k0;
        *(u64*)(g_W1h + off) = H;
        *(u64*)(g_W1l + off) = L;
    } else if (blk < 192) {
        const int w    = (blk - 96) * 12 + (tid >> 5);
        const int lane = tid & 31;
        const int g = w / D3, o = w - g * D3;
        const float* S = (g == 0) ? Sq : (g == 1) ? Sk : Sv;
        const float* b = (g == 0) ? bq : (g == 1) ? bk : bv;
        float acc = 0.0f;
#pragma unroll
        for (int i = 0; i < 12; i++) {
            int m = lane + i * 32;
            acc = fmaf(S[m * D3 + o], b[m], acc);
        }
#pragma unroll
        for (int off = 16; off > 0; off >>= 1)
            acc += __shfl_down_sync(0xffffffffu, acc, off);
        if (lane == 0) g_fb[w] = acc;
    } else {
        const int b = blk - 192;
        const int k = tid;
#pragma unroll
        for (int r = 0; r < 12; r++) {
            int o = b * 12 + r;
            float v = sp_fast(Wp[o * D3 + k]);
            uint16_t h, l;
            wsplit(v, h, l);
            size_t off = (size_t)((k >> 7) * 9 + (o >> 7)) * 16384
                       + (o & 127) * 128 + (k & 127);
            g_W2h[off] = __ushort_as_bfloat16(h);
            g_W2l[off] = __ushort_as_bfloat16(l);
        }
    }
}

// -------------------- K1/K3: HMMA dual-bf16 GEMM (R12 tile + LDSM frags) ----
// C[2048,1152] = A[2048,384] @ W[384,1152] + bias  (AhBh + AhBl + AlBh)
// grid (16, 9); 8 warps = 4(m) x 2(n); warp tile 32x64; M-tile 128.
template <int MODE>
__global__ __launch_bounds__(256) void k_gemm_mma(const float* __restrict__ Ax,
                                                  const float* __restrict__ bext) {
    __shared__ __nv_bfloat16 sAh[128 * PAD];
    __shared__ __nv_bfloat16 sAl[128 * PAD];
    __shared__ __nv_bfloat16 sBh[128 * PAD];
    __shared__ __nv_bfloat16 sBl[128 * PAD];

    const int tid  = threadIdx.x;
    const int lane = tid & 31, wid = tid >> 5;
    const int g    = lane >> 2, tig = lane & 3;
    const int wm   = wid & 3,  wn  = wid >> 2;       // 4(m) x 2(n)
    const int m0   = wm * 32,  n0  = wn * 64;
    const int t0   = blockIdx.x * 128;
    const int jn   = blockIdx.y;

    const __nv_bfloat16* Wh = (MODE == 0) ? g_W1h : g_W2h;
    const __nv_bfloat16* Wl = (MODE == 0) ? g_W1l : g_W2l;
    float*       Cout = (MODE == 0) ? g_QKV : g_h;
    const float* bias = (MODE == 0) ? g_fb  : bext;
    const int nch = (MODE == 0) ? 4 : 12;

    // shared-state u32 base addresses for ldmatrix
    const uint32_t uAh = (uint32_t)__cvta_generic_to_shared(sAh);
    const uint32_t uAl = (uint32_t)__cvta_generic_to_shared(sAl);
    const uint32_t uBh = (uint32_t)__cvta_generic_to_shared(sBh);
    const uint32_t uBl = (uint32_t)__cvta_generic_to_shared(sBl);
    // A: row = m0 + f*16 + (lane&15), col = kk + (lane>>4)*8
    const uint32_t aLane = (uint32_t)((m0 + (lane & 15)) * PAD + ((lane >> 4) << 3));
    // B x4 covers nf pair p: row = n0 + 16p + (lane>>4)*8 + (lane&7), col = kk + (lane&8)
    const uint32_t bLane = (uint32_t)((((lane >> 4) << 3) + (lane & 7) + n0) * PAD
                                      + (lane & 8));

    float acc[2][8][4];
#pragma unroll
    for (int f = 0; f < 2; f++)
#pragma unroll
        for (int nf = 0; nf < 8; nf++)
#pragma unroll
            for (int i = 0; i < 4; i++) acc[f][nf][i] = 0.f;

    float4 afr[4];
    uint4  pfr[8];

    auto ldch = [&](int ch) {
        const int acol  = (MODE == 0) ? ((jn / 3) * 128 + ch * 32) : (ch * 32);
        const int wtile = (MODE == 0) ? jn : ((ch >> 2) * 9 + jn);
        const int wcol  = (MODE == 0) ? (ch * 32) : ((ch & 3) * 32);
        if (MODE == 0) {
#pragma unroll
            for (int j = 0; j < 4; j++) {
                int idx = tid + (j << 8);
                int row = idx >> 3, k4 = (idx & 7) << 2;
                afr[j] = *(const float4*)(Ax + (size_t)(t0 + row) * D3 + acol + k4);
            }
        } else {
#pragma unroll
            for (int j = 0; j < 4; j++) {
                int idx = tid + ((j & 1) << 8);
                int row = idx >> 2, seg = (idx & 3) << 3;
                const __nv_bfloat16* src = ((j < 2) ? g_Ath : g_Atl)
                    + (size_t)(t0 + row) * D3 + acol + seg;
                pfr[j] = *(const uint4*)src;
            }
        }
#pragma unroll
        for (int j = 4; j < 8; j++) {
            int idx = tid + ((j & 1) << 8);
            int row = idx >> 2, seg = (idx & 3) << 3;
            const __nv_bfloat16* src = ((j < 6) ? Wh : Wl)
                + (size_t)wtile * 16384 + row * 128 + wcol + seg;
            pfr[j] = *(const uint4*)src;
        }
    };
    auto stch = [&]() {
        if (MODE == 0) {
#pragma unroll
            for (int j = 0; j < 4; j++) {
                int idx = tid + (j << 8);
                int row = idx >> 3, k4 = (idx & 7) << 2;
                uint16_t h0, l0, h1, l1, h2, l2, h3, l3;
                wsplit(afr[j].x, h0, l0); wsplit(afr[j].y, h1, l1);
                wsplit(afr[j].z, h2, l2); wsplit(afr[j].w, h3, l3);
                u64 H = (u64)h0 | ((u64)h1 << 16) | ((u64)h2 << 32) | ((u64)h3 << 48);
                u64 L = (u64)l0 | ((u64)l1 << 16) | ((u64)l2 << 32) | ((u64)l3 << 48);
                *(u64*)(sAh + row * PAD + k4) = H;
                *(u64*)(sAl + row * PAD + k4) = L;
            }
        } else {
#pragma unroll
            for (int j = 0; j < 4; j++) {
                int idx = tid + ((j & 1) << 8);
                int row = idx >> 2, seg = (idx & 3) << 3;
                *(uint4*)(((j < 2) ? sAh : sAl) + row * PAD + seg) = pfr[j];
            }
        }
#pragma unroll
        for (int j = 4; j < 8; j++) {
            int idx = tid + ((j & 1) << 8);
            int row = idx >> 2, seg = (idx & 3) << 3;
            *(uint4*)(((j < 6) ? sBh : sBl) + row * PAD + seg) = pfr[j];
        }
    };

    ldch(0);
    for (int ch = 0; ch < nch; ch++) {
        stch();
        __syncthreads();
        if (ch + 1 < nch) ldch(ch + 1);

#pragma unroll
        for (int kk = 0; kk < 32; kk += 16) {
            uint32_t ah[2][4], al[2][4];
#pragma unroll
            for (int f = 0; f < 2; f++) {
                uint32_t ao = (aLane + f * 16 * PAD + kk) * 2u;  // byte offset
                ldsm4(ah[f], uAh + ao);
                ldsm4(al[f], uAl + ao);
            }
            uint32_t bh[16], bl[16];
#pragma unroll
            for (int p = 0; p < 4; p++) {                        // nf pairs
                uint32_t bo = (bLane + p * 16 * PAD + kk) * 2u;
                ldsm4(bh + 4 * p, uBh + bo);
                ldsm4(bl + 4 * p, uBl + bo);
            }
#pragma unroll
            for (int nf = 0; nf < 8; nf++) {
                uint32_t bh0 = bh[2 * nf], bh1 = bh[2 * nf + 1];
                uint32_t bl0 = bl[2 * nf], bl1 = bl[2 * nf + 1];
#pragma unroll
                for (int f = 0; f < 2; f++) {
                    mma16816(acc[f][nf], ah[f], bh0, bh1);
                    mma16816(acc[f][nf], ah[f], bl0, bl1);
                    mma16816(acc[f][nf], al[f], bh0, bh1);
                }
            }
        }
        __syncthreads();
    }

#pragma unroll
    for (int f = 0; f < 2; f++) {
        int row = t0 + m0 + f * 16 + g;
#pragma unroll
        for (int nf = 0; nf < 8; nf++) {
            int col = jn * 128 + n0 + nf * 8 + tig * 2;
            float b0v = bias[col], b1v = bias[col + 1];
            float2 lo = make_float2(acc[f][nf][0] + b0v, acc[f][nf][1] + b1v);
            float2 hi = make_float2(acc[f][nf][2] + b0v, acc[f][nf][3] + b1v);
            *(float2*)(Cout + (size_t)row * D9 + col)       = lo;
            *(float2*)(Cout + (size_t)(row + 8) * D9 + col) = hi;
        }
    }
}

// -------------------- K2: prefix-band attention (bin-aggregate tails) -------
// (verbatim R12 kernel -- proven at 110.6us total)
__global__ __launch_bounds__(384) void k_attn() {
    __shared__ float2 s[D3];
    __shared__ int    off[NBINS + 1];
    __shared__ int    cnt[NBINS],  cur[NBINS];
    __shared__ int    qcnt[NBINS], qcur[NBINS];
    __shared__ float  binS[NBINS], binSV[NBINS];
    __shared__ float  PS[NBINS + 1], PSV[NBINS + 1];
    __shared__ int    wtot[4], qwtot[4];
    __shared__ float2 fwtot[4];
    __shared__ float  rmax[12], rsum[12];
    __shared__ float  s_inv, s_sumv;
    __shared__ float  sqv[D3];
    __shared__ int    qlist[D3];
    __shared__ float  satt[D3];

    const int t    = blockIdx.x;
    const int tid  = threadIdx.x;
    const int lane = tid & 31, wid = tid >> 5;
    const float* base = g_QKV + (size_t)t * D9;

    const float q  = base[tid];
    const float c  = base[D3 + tid] * HALF_GAMMA;
    const float v  = base[2 * D3 + tid];
    const float ac = fabsf(c);
    const float sg = (c >= 0.f) ? 1.f : -1.f;
    sqv[tid] = q;

    float mx = ac, sv = v;
#pragma unroll
    for (int o = 16; o > 0; o >>= 1) {
        mx = fmaxf(mx, __shfl_down_sync(0xffffffffu, mx, o));
        sv += __shfl_down_sync(0xffffffffu, sv, o);
    }
    if (lane == 0) { rmax[wid] = mx; rsum[wid] = sv; }
    if (tid < NBINS) {
        cnt[tid] = 0; qcnt[tid] = 0;
        binS[tid] = 0.f; binSV[tid] = 0.f;
    }
    __syncthreads();
    if (tid == 0) {
        float m = rmax[0], s2 = rsum[0];
#pragma unroll
        for (int i = 1; i < 12; i++) { m = fmaxf(m, rmax[i]); s2 += rsum[i]; }
        s_inv  = 127.99f / (m + 1e-12f);
        s_sumv = s2;
    }
    __syncthreads();
    const float inv = s_inv;

    const int b  = (int)(ac * inv);
    const float th = TANH_SAT / fabsf(q);
    const int bt = (int)fminf(th * inv, 127.0f);
    atomicAdd(&cnt[b], 1);
    atomicAdd(&qcnt[bt], 1);
    atomicAdd(&binS[b], sg);
    atomicAdd(&binSV[b], sg * v);
    __syncthreads();

    if (wid < 8) {
        int i2 = tid & 127;
        int xval = (wid < 4) ? cnt[i2] : qcnt[i2];
        int incl = xval;
#pragma unroll
        for (int o = 1; o < 32; o <<= 1) {
            int nb = __shfl_up_sync(0xffffffffu, incl, o);
            if (lane >= o) incl += nb;
        }
        if (lane == 31) {
            if (wid < 4) wtot[wid] = incl;
            else         qwtot[wid - 4] = incl;
        }
        __syncthreads();
        int wq = wid & 3;
        int add = 0;
        const int* tot = (wid < 4) ? wtot : qwtot;
#pragma unroll
        for (int w = 0; w < 4; w++) if (w < wq) add += tot[w];
        if (wid < 4) {
            off[i2 + 1] = incl + add;
            cur[i2]     = incl + add - xval;
            if (i2 == 0) off[0] = 0;
        } else {
            qcur[i2] = incl + add - xval;
        }
    } else {
        int i2 = tid - 256;
        float iS = binS[i2], iV = binSV[i2];
#pragma unroll
        for (int o = 1; o < 32; o <<= 1) {
            float ax = __shfl_up_sync(0xffffffffu, iS, o);
            float ay = __shfl_up_sync(0xffffffffu, iV, o);
            if (lane >= o) { iS += ax; iV += ay; }
        }
        if (lane == 31) fwtot[wid - 8] = make_float2(iS, iV);
        __syncthreads();
        int wq = wid - 8;
        float aS = 0.f, aV = 0.f;
#pragma unroll
        for (int w = 0; w < 4; w++)
            if (w < wq) { aS += fwtot[w].x; aV += fwtot[w].y; }
        PS [i2 + 1] = iS + aS;
        PSV[i2 + 1] = iV + aV;
        if (i2 == 0) { PS[0] = 0.f; PSV[0] = 0.f; }
    }
    __syncthreads();

    {
        int pos = atomicAdd(&cur[b], 1);
        s[pos] = make_float2(c, v);
        int n  = off[bt + 1];
        int qpos = atomicAdd(&qcur[bt], 1);
        qlist[qpos] = tid | (n << 9) | (bt << 18);
    }
    __syncthreads();

    const int   e   = qlist[tid];
    const int   qi  = e & 511;
    const int   nn  = (e >> 9) & 511;
    const int   btq = (e >> 18) & 127;
    const float qq  = sqv[qi];
    int nmax = nn;
#pragma unroll
    for (int o = 16; o > 0; o >>= 1)
        nmax = max(nmax, __shfl_xor_sync(0xffffffffu, nmax, o));

    float ts = 0.f, tv = 0.f;
#pragma unroll 4
    for (int j = 0; j < nmax; j++) {
        float2 cv = s[j];
        if (j < nn) {
            float tt = fast_tanh(qq * cv.x);
            tv = fmaf(tt, cv.y, tv);
            ts += tt;
        }
    }
    const float sgq = (qq >= 0.f) ? 1.f : -1.f;
    ts += sgq * (PS [NBINS] - PS [btq + 1]);
    tv += sgq * (PSV[NBINS] - PSV[btq + 1]);
    float num = fmaf(0.5f, tv, 0.5f * s_sumv);
    float den = fmaf(0.5f, ts, 192.0f + 1e-8f);
    satt[qi] = num / den;
    __syncthreads();

    uint16_t hh, ll;
    wsplit(satt[tid], hh, ll);
    g_Ath[(size_t)t * D3 + tid] = __ushort_as_bfloat16(hh);
    g_Atl[(size_t)t * D3 + tid] = __ushort_as_bfloat16(ll);
}

// -------------------- K4: LayerNorm, 2 tokens/CTA, two-pass -----------------
__global__ __launch_bounds__(384) void k_ln(const float* __restrict__ gn,
                                            const float* __restrict__ bn,
                                            float* __restrict__ out) {
    __shared__ float red[2][6];
    __shared__ float stat[2][2];
    const int tid  = threadIdx.x;
    const int wid  = tid >> 5, lane = tid & 31;
    const int half = (wid >= 6);
    const int widh = wid - half * 6;
    const int tidh = tid - half * 192;
    const int t    = blockIdx.x * 2 + half;
    const float* h = g_h + (size_t)t * D9;

    float v[6];
#pragma unroll
    for (int j = 0; j < 6; j++) v[j] = h[tidh + 192 * j];

    float s = 0.f;
#pragma unroll
    for (int j = 0; j < 6; j++) s += v[j];
#pragma unroll
    for (int o = 16; o > 0; o >>= 1) s += __shfl_down_sync(0xffffffffu, s, o);
    if (lane == 0) red[half][widh] = s;
    __syncthreads();
    if (tidh == 0) {
        float tot = 0.f;
#pragma unroll
        for (int i = 0; i < 6; i++) tot += red[half][i];
        stat[half][0] = tot * (1.0f / 1152.0f);
    }
    __syncthreads();
    const float mu = stat[half][0];

    float d[6];
    float ss = 0.f;
#pragma unroll
    for (int j = 0; j < 6; j++) { d[j] = v[j] - mu; ss += d[j] * d[j]; }
#pragma unroll
    for (int o = 16; o > 0; o >>= 1) ss += __shfl_down_sync(0xffffffffu, ss, o);
    if (lane == 0) red[half][widh] = ss;
    __syncthreads();
    if (tidh == 0) {
        float tot = 0.f;
#pragma unroll
        for (int i = 0; i < 6; i++) tot += red[half][i];
        stat[half][1] = rsqrtf(tot * (1.0f / 1152.0f) + 1e-5f);
    }
    __syncthreads();
    const float rs = stat[half][1];

    float* o = out + (size_t)t * D9;
#pragma unroll
    for (int j = 0; j < 6; j++) {
        int idx = tidh + 192 * j;
        o[idx] = d[j] * rs * gn[idx] + bn[idx];
    }
}

// -------------------- launch -------------------------------------------------
extern "C" void kernel_launch(void* const* d_in, const int* in_sizes, int n_in,
                              void* d_out, int out_size) {
    const float* x  = (const float*)d_in[0];
    const float* Wq = (const float*)d_in[1];
    const float* bq = (const float*)d_in[2];
    const float* Sq = (const float*)d_in[3];
    const float* Wk = (const float*)d_in[4];
    const float* bk = (const float*)d_in[5];
    const float* Sk = (const float*)d_in[6];
    const float* Wv = (const float*)d_in[7];
    const float* bv = (const float*)d_in[8];
    const float* Sv = (const float*)d_in[9];
    const float* Wp = (const float*)d_in[10];
    const float* bp = (const float*)d_in[11];
    const float* gn = (const float*)d_in[12];
    const float* bn = (const float*)d_in[13];
    float* out = (float*)d_out;

    // 5 launches; profiled slot (#4) = k_gemm_mma<1> (LDSM check)
    k_prep       <<<288, 384>>>(Wq, Wk, Wv, Sq, Sk, Sv, bq, bk, bv, Wp);
    k_gemm_mma<0><<<dim3(16, 9), 256>>>(x, nullptr);
    k_attn       <<<NTOK, 384>>>();
    k_gemm_mma<1><<<dim3(16, 9), 256>>>(nullptr, bp);
    k_ln         <<<NTOK / 2, 384>>>(gn, bn, out);
}